// round 16
// baseline (speedup 1.0000x reference)
#include <cuda_runtime.h>
#include <cuda_bf16.h>
#include <math.h>
#include <stdint.h>

#define NV 4000
#define NL 8000          // 2*NV literals
#define NC 16800
#define NE 50400         // NC*3 edges
#define FM 256
#define ROUNDS 32

// ---------------------------------------------------------------------------
// PTX helpers (baseline ISA only: ldmatrix + mma.sync + cp.async, sm_80+)
// ---------------------------------------------------------------------------
__device__ __forceinline__ uint32_t smem_u32(const void* p) {
    uint32_t a;
    asm("{ .reg .u64 t; cvta.to.shared.u64 t, %1; cvt.u32.u64 %0, t; }"
        : "=r"(a) : "l"(p));
    return a;
}
__device__ __forceinline__ void ldsm_x4(uint32_t& r0, uint32_t& r1,
                                        uint32_t& r2, uint32_t& r3, uint32_t a) {
    asm volatile("ldmatrix.sync.aligned.m8n8.x4.shared.b16 {%0,%1,%2,%3}, [%4];"
                 : "=r"(r0), "=r"(r1), "=r"(r2), "=r"(r3) : "r"(a));
}
__device__ __forceinline__ void ldsm_x2(uint32_t& r0, uint32_t& r1, uint32_t a) {
    asm volatile("ldmatrix.sync.aligned.m8n8.x2.shared.b16 {%0,%1}, [%2];"
                 : "=r"(r0), "=r"(r1) : "r"(a));
}
__device__ __forceinline__ void mma_bf16(float* c, const uint32_t* a,
                                         const uint32_t* b) {
    asm volatile(
        "mma.sync.aligned.m16n8k16.row.col.f32.bf16.bf16.f32 "
        "{%0,%1,%2,%3}, {%4,%5,%6,%7}, {%8,%9}, {%0,%1,%2,%3};"
        : "+f"(c[0]), "+f"(c[1]), "+f"(c[2]), "+f"(c[3])
        : "r"(a[0]), "r"(a[1]), "r"(a[2]), "r"(a[3]), "r"(b[0]), "r"(b[1]));
}
__device__ __forceinline__ void cpasync16(uint32_t saddr, const void* g) {
    asm volatile("cp.async.cg.shared.global [%0], [%1], 16;"
                 :: "r"(saddr), "l"(g) : "memory");
}
__device__ __forceinline__ void cpasync16z(uint32_t saddr, const void* g, int ssz) {
    asm volatile("cp.async.cg.shared.global [%0], [%1], 16, %2;"
                 :: "r"(saddr), "l"(g), "r"(ssz) : "memory");
}
#define CPASYNC_COMMIT() asm volatile("cp.async.commit_group;" ::: "memory")
#define CPASYNC_WAIT0()  asm volatile("cp.async.wait_group 0;" ::: "memory")

#define SWZ128(off) ((off) ^ (((off) >> 3) & 0x70))

// ---------------------------------------------------------------------------
// Scratch (static device globals)
// Activations are stored PRE-SPLIT as bf16 hi/lo pairs (hi array, then lo).
// ---------------------------------------------------------------------------
__device__ __nv_bfloat16 g_lhB[2 * NL * FM];
__device__ __nv_bfloat16 g_chB[2 * NC * FM];
__device__ __nv_bfloat16 g_b1B[2 * NC * FM];
__device__ __nv_bfloat16 g_b2B[2 * NC * FM];
__device__ __nv_bfloat16 g_msgcB[2 * NC * FM];
__device__ __nv_bfloat16 g_msglB[2 * NL * FM];
__device__ __nv_bfloat16 g_v1B[2 * NV * 2 * FM];
__device__ float g_pre[NC * FM];     // fp32 MLP output feeding gathers
__device__ float g_zc[NC * 4 * FM];
__device__ float g_zl[NL * 4 * FM];
__device__ float g_cc[NC * FM];
__device__ float g_lc[NL * FM];
__device__ float g_v2[NV * 2 * FM];
__device__ float g_logits[NV];
__device__ float g_loss;

__device__ int g_lit[NE];
__device__ int g_cnt[NL];
__device__ int g_off[NL + 1];
__device__ int g_ledges[NE];

// weight pool: transposed [N,K] bf16, hi then lo halves
#define WTOT 2228224
__device__ __nv_bfloat16 g_wpool[2 * WTOT];

__device__ __forceinline__ void split_write(__nv_bfloat16* hi, __nv_bfloat16* lo,
                                            size_t idx, float v) {
    __nv_bfloat16 h = __float2bfloat16_rn(v);
    hi[idx] = h;
    lo[idx] = __float2bfloat16_rn(v - __bfloat162float(h));
}

// ---------------------------------------------------------------------------
// Edge preprocessing (unchanged, known-correct)
// ---------------------------------------------------------------------------
__global__ void edge_prep_kernel(const int* __restrict__ lits) {
    int e = blockIdx.x * blockDim.x + threadIdx.x;
    if (e >= NE) return;
    int v = lits[e];
    int va = (v > 0 ? v : -v) - 1;
    g_lit[e] = (v > 0) ? va : (NV + va);
}
__global__ void zero_cnt_kernel() {
    int i = blockIdx.x * blockDim.x + threadIdx.x;
    if (i < NL) g_cnt[i] = 0;
}
__global__ void count_kernel() {
    int e = blockIdx.x * blockDim.x + threadIdx.x;
    if (e < NE) atomicAdd(&g_cnt[g_lit[e]], 1);
}
__global__ void scan_kernel() {
    __shared__ int part[1024];
    const int t = threadIdx.x;
    const int CH = 8;
    int base = t * CH;
    int local[CH];
    int s = 0;
    #pragma unroll
    for (int i = 0; i < CH; i++) {
        int idx = base + i;
        int v = (idx < NL) ? g_cnt[idx] : 0;
        local[i] = s;
        s += v;
    }
    part[t] = s;
    __syncthreads();
    for (int d = 1; d < 1024; d <<= 1) {
        int v = (t >= d) ? part[t - d] : 0;
        __syncthreads();
        part[t] += v;
        __syncthreads();
    }
    int off = (t == 0) ? 0 : part[t - 1];
    #pragma unroll
    for (int i = 0; i < CH; i++) {
        int idx = base + i;
        if (idx < NL) g_off[idx] = off + local[i];
    }
    if (t == 1023) g_off[NL] = part[1023];
}
__global__ void fill_kernel() {
    int e = blockIdx.x * blockDim.x + threadIdx.x;
    if (e >= NE) return;
    int l = g_lit[e];
    int pos = atomicAdd(&g_cnt[l], 1);
    g_ledges[g_off[l] + pos] = e;
}
__global__ void sort_kernel() {
    int l = blockIdx.x * blockDim.x + threadIdx.x;
    if (l >= NL) return;
    int beg = g_off[l], end = g_off[l + 1];
    for (int i = beg + 1; i < end; i++) {
        int key = g_ledges[i];
        int j = i - 1;
        while (j >= beg && g_ledges[j] > key) {
            g_ledges[j + 1] = g_ledges[j];
            j--;
        }
        g_ledges[j + 1] = key;
    }
}
__global__ void init_state_kernel(const float* __restrict__ Li,
                                  const float* __restrict__ Ci) {
    int idx = blockIdx.x * blockDim.x + threadIdx.x;
    const float inv = 0.0625f;
    if (idx < NL * FM) {
        split_write(g_lhB, g_lhB + NL * FM, idx, Li[idx & (FM - 1)] * inv);
        g_lc[idx] = 0.f;
    }
    if (idx < NC * FM) {
        split_write(g_chB, g_chB + NC * FM, idx, Ci[idx & (FM - 1)] * inv);
        g_cc[idx] = 0.f;
    }
    if (idx == 0) g_loss = 0.f;
}

// ---------------------------------------------------------------------------
// Weight split+transpose: src fp32 [K,N] -> pool hi/lo bf16 [N,K]
// ---------------------------------------------------------------------------
__global__ void wsplit_kernel(const float* __restrict__ src, int K, int N, int off) {
    int idx = blockIdx.x * blockDim.x + threadIdx.x;
    if (idx >= K * N) return;
    int k = idx / N, n = idx - k * N;
    float v = src[idx];
    __nv_bfloat16 h = __float2bfloat16_rn(v);
    __nv_bfloat16 l = __float2bfloat16_rn(v - __bfloat162float(h));
    g_wpool[off + (size_t)n * K + k] = h;
    g_wpool[WTOT + off + (size_t)n * K + k] = l;
}

// ---------------------------------------------------------------------------
// Tensor-core GEMM (mma.sync bf16, fp32 accum, Markidis 3-term split):
//   C[M,N] = concat_K(A1,A2,A3) @ concat_rows(W1,W2,W3) (+bias)(relu)
// A inputs are PRE-SPLIT bf16 hi/lo [M,K]; staging is pure cp.async.
// BM=64, BN=128, BK=64; warp tile 32x32; 48KB smem; 3 CTAs/SM.
// GF_FLIP2: segment-2 rows read flip-permuted (l<NV -> l+NV else l-NV).
// GF_SPLIT: output written as split bf16 hi/lo (Ch/Cl) instead of fp32 C.
// ---------------------------------------------------------------------------
#define GF_RELU 1
#define GF_FLIP2 4
#define GF_SPLIT 16
#define TG_SMEM 49152

__global__ __launch_bounds__(256, 3)
void tgemm_kernel(const __nv_bfloat16* __restrict__ A1h,
                  const __nv_bfloat16* __restrict__ A1l, int K1,
                  const __nv_bfloat16* __restrict__ B1h,
                  const __nv_bfloat16* __restrict__ B1l,
                  const __nv_bfloat16* __restrict__ A2h,
                  const __nv_bfloat16* __restrict__ A2l, int K2,
                  const __nv_bfloat16* __restrict__ B2h,
                  const __nv_bfloat16* __restrict__ B2l,
                  const __nv_bfloat16* __restrict__ A3h,
                  const __nv_bfloat16* __restrict__ A3l, int K3,
                  const __nv_bfloat16* __restrict__ B3h,
                  const __nv_bfloat16* __restrict__ B3l,
                  const float* __restrict__ bias, float* __restrict__ C,
                  __nv_bfloat16* __restrict__ Ch, __nv_bfloat16* __restrict__ Cl,
                  int M, int N, int flags) {
    extern __shared__ char smem[];
    const uint32_t sb0 = smem_u32(smem);
    const uint32_t sAh = sb0, sAl = sb0 + 8192;          // 64 rows x 128B each
    const uint32_t sBh = sb0 + 16384, sBl = sb0 + 32768; // 128 rows x 128B each

    const int tid = threadIdx.x;
    const int wid = tid >> 5, lid = tid & 31;
    const int bm = blockIdx.y * 64;
    const int bn = blockIdx.x * 128;
    const int wm = (wid & 1) * 32;     // 2 warp-rows x 32
    const int wn = (wid >> 1) * 32;    // 4 warp-cols x 32

    float acc[2][4][4];
    #pragma unroll
    for (int i = 0; i < 2; i++)
        #pragma unroll
        for (int j = 0; j < 4; j++)
            #pragma unroll
            for (int q = 0; q < 4; q++) acc[i][j][q] = 0.f;

    const int nch = (K1 + K2 + K3) >> 6;

    for (int c = 0; c < nch; c++) {
        int kk0 = c << 6;
        const __nv_bfloat16 *ah = A1h, *al = A1l, *bh = B1h, *bl = B1l;
        int ldk = K1, kk = kk0, flip = 0;
        if (kk0 >= K1 + K2) {
            ah = A3h; al = A3l; bh = B3h; bl = B3l; ldk = K3; kk = kk0 - K1 - K2;
        } else if (kk0 >= K1) {
            ah = A2h; al = A2l; bh = B2h; bl = B2l; ldk = K2;
            kk = kk0 - K1; flip = (flags & GF_FLIP2);
        }

        __syncthreads();   // protect tiles from previous iteration's readers

        // ---- A stage: 64 rows, hi+lo = 1024 x 16B chunks (4 per thread) ----
        #pragma unroll
        for (int i = 0; i < 4; i++) {
            int idx = i * 256 + tid;           // 0..1023
            int half = idx >> 9;               // 0: hi, 1: lo
            int j = idx & 511;
            int row = j >> 3;                  // m local 0..63
            int c16 = (j & 7) << 4;            // byte offset 0..112
            int gr = bm + row;
            int inb = (gr < M);
            int ar = inb ? gr : 0;
            if (flip) ar = (ar < NV) ? ar + NV : ar - NV;
            const __nv_bfloat16* src =
                (half ? al : ah) + (size_t)ar * ldk + kk + (c16 >> 1);
            cpasync16z((half ? sAl : sAh) + SWZ128((uint32_t)(row * 128 + c16)),
                       src, inb ? 16 : 0);
        }

        // ---- B stage: 128 rows, hi+lo = 2048 x 16B chunks (8 per thread) ----
        #pragma unroll
        for (int i = 0; i < 8; i++) {
            int idx = i * 256 + tid;
            int half = idx >> 10;
            int j = idx & 1023;
            int row = j >> 3;                  // n local 0..127
            int c16 = (j & 7) << 4;
            const __nv_bfloat16* src =
                (half ? bl : bh) + (size_t)(bn + row) * ldk + kk + (c16 >> 1);
            cpasync16((half ? sBl : sBh) + SWZ128((uint32_t)(row * 128 + c16)),
                      src);
        }
        CPASYNC_COMMIT();
        CPASYNC_WAIT0();
        __syncthreads();

        // ---- compute: 4 k16 steps ----
        #pragma unroll
        for (int s = 0; s < 4; s++) {
            int kb = s * 32;
            uint32_t ahf[2][4], alf[2][4], bhf[4][2], blf[4][2];
            int arow = (lid & 15);
            int acolb = kb + (lid >> 4) * 16;
            #pragma unroll
            for (int mt = 0; mt < 2; mt++) {
                uint32_t o = SWZ128((uint32_t)((wm + mt * 16 + arow) * 128 + acolb));
                ldsm_x4(ahf[mt][0], ahf[mt][1], ahf[mt][2], ahf[mt][3], sAh + o);
                ldsm_x4(alf[mt][0], alf[mt][1], alf[mt][2], alf[mt][3], sAl + o);
            }
            int brow = (lid & 7);
            int bcolb = kb + ((lid >> 3) & 1) * 16;
            #pragma unroll
            for (int nt = 0; nt < 4; nt++) {
                uint32_t o = SWZ128((uint32_t)((wn + nt * 8 + brow) * 128 + bcolb));
                ldsm_x2(bhf[nt][0], bhf[nt][1], sBh + o);
                ldsm_x2(blf[nt][0], blf[nt][1], sBl + o);
            }
            #pragma unroll
            for (int mt = 0; mt < 2; mt++)
                #pragma unroll
                for (int nt = 0; nt < 4; nt++) {
                    mma_bf16(acc[mt][nt], ahf[mt], bhf[nt]);
                    mma_bf16(acc[mt][nt], alf[mt], bhf[nt]);
                    mma_bf16(acc[mt][nt], ahf[mt], blf[nt]);
                }
        }
    }

    // ---- epilogue ----
    #pragma unroll
    for (int mt = 0; mt < 2; mt++) {
        int r0 = bm + wm + mt * 16 + (lid >> 2);
        #pragma unroll
        for (int nt = 0; nt < 4; nt++) {
            int col = bn + wn + nt * 8 + (lid & 3) * 2;
            float bx = 0.f, by = 0.f;
            if (bias) { bx = bias[col]; by = bias[col + 1]; }
            float2 v0 = make_float2(acc[mt][nt][0] + bx, acc[mt][nt][1] + by);
            float2 v1 = make_float2(acc[mt][nt][2] + bx, acc[mt][nt][3] + by);
            if (flags & GF_RELU) {
                v0.x = fmaxf(v0.x, 0.f); v0.y = fmaxf(v0.y, 0.f);
                v1.x = fmaxf(v1.x, 0.f); v1.y = fmaxf(v1.y, 0.f);
            }
            if (flags & GF_SPLIT) {
                if (r0 < M) {
                    size_t ix = (size_t)r0 * N + col;
                    __nv_bfloat16 h0 = __float2bfloat16_rn(v0.x);
                    __nv_bfloat16 h1 = __float2bfloat16_rn(v0.y);
                    __nv_bfloat162 hi = __halves2bfloat162(h0, h1);
                    *(uint32_t*)&Ch[ix] = *(uint32_t*)&hi;
                    __nv_bfloat162 lo = __halves2bfloat162(
                        __float2bfloat16_rn(v0.x - __bfloat162float(h0)),
                        __float2bfloat16_rn(v0.y - __bfloat162float(h1)));
                    *(uint32_t*)&Cl[ix] = *(uint32_t*)&lo;
                }
                if (r0 + 8 < M) {
                    size_t ix = (size_t)(r0 + 8) * N + col;
                    __nv_bfloat16 h0 = __float2bfloat16_rn(v1.x);
                    __nv_bfloat16 h1 = __float2bfloat16_rn(v1.y);
                    __nv_bfloat162 hi = __halves2bfloat162(h0, h1);
                    *(uint32_t*)&Ch[ix] = *(uint32_t*)&hi;
                    __nv_bfloat162 lo = __halves2bfloat162(
                        __float2bfloat16_rn(v1.x - __bfloat162float(h0)),
                        __float2bfloat16_rn(v1.y - __bfloat162float(h1)));
                    *(uint32_t*)&Cl[ix] = *(uint32_t*)&lo;
                }
            } else {
                if (r0 < M)     *(float2*)&C[(size_t)r0 * N + col] = v0;
                if (r0 + 8 < M) *(float2*)&C[(size_t)(r0 + 8) * N + col] = v1;
            }
        }
    }
}

// ---------------------------------------------------------------------------
// Elementwise / gather kernels
// ---------------------------------------------------------------------------
__device__ __forceinline__ float sigm(float x) { return 1.f / (1.f + expf(-x)); }

// LSTM elementwise: z fp32 (gate-blocked), c fp32 in/out, h written SPLIT bf16.
__global__ void lstm_kernel(const float* __restrict__ z,
                            __nv_bfloat16* __restrict__ hB, size_t loOff,
                            float* __restrict__ c, int R) {
    int idx = blockIdx.x * blockDim.x + threadIdx.x;
    if (idx >= R * FM) return;
    int r = idx / FM, f = idx - r * FM;
    const float* zr = z + (size_t)r * 4 * FM;
    float zi = zr[f], zf = zr[FM + f], zg = zr[2 * FM + f], zo = zr[3 * FM + f];
    float cv = sigm(zf) * c[idx] + sigm(zi) * tanhf(zg);
    c[idx] = cv;
    float hv = sigm(zo) * tanhf(cv);
    split_write(hB, hB + loOff, idx, hv);
}

__global__ void clause_gather_kernel(const float* __restrict__ pre,
                                     __nv_bfloat16* __restrict__ outB) {
    int c = blockIdx.x;
    int f = threadIdx.x;
    int e0 = c * 3;
    float s = pre[(size_t)g_lit[e0] * FM + f] +
              pre[(size_t)g_lit[e0 + 1] * FM + f] +
              pre[(size_t)g_lit[e0 + 2] * FM + f];
    split_write(outB, outB + (size_t)NC * FM, (size_t)c * FM + f, s);
}

__global__ void lit_gather_kernel(const float* __restrict__ cl_pre,
                                  __nv_bfloat16* __restrict__ outB) {
    int l = blockIdx.x;
    int f = threadIdx.x;
    int beg = g_off[l], end = g_off[l + 1];
    float s = 0.f;
    for (int i = beg; i < end; i++) {
        int e = g_ledges[i];
        s += cl_pre[(size_t)(e / 3) * FM + f];
    }
    split_write(outB, outB + (size_t)NL * FM, (size_t)l * FM + f, s);
}

__global__ void vote_out_kernel(const float* __restrict__ H,
                                const float* __restrict__ W,
                                const float* __restrict__ b) {
    int r = blockIdx.x;
    float s = 0.f;
    for (int k = threadIdx.x; k < 2 * FM; k += blockDim.x)
        s += H[(size_t)r * 2 * FM + k] * W[k];
    for (int o = 16; o; o >>= 1) s += __shfl_down_sync(0xffffffffu, s, o);
    __shared__ float sm[4];
    if ((threadIdx.x & 31) == 0) sm[threadIdx.x >> 5] = s;
    __syncthreads();
    if (threadIdx.x == 0)
        g_logits[r] = sm[0] + sm[1] + sm[2] + sm[3] + b[0];
}

__device__ __forceinline__ float softplus_f(float x) {
    return x > 0.f ? x + log1pf(expf(-x)) : log1pf(expf(x));
}

__global__ void loss_kernel() {
    int c = blockIdx.x * blockDim.x + threadIdx.x;
    float t = 0.f;
    if (c < NC) {
        float s = 0.f;
        #pragma unroll
        for (int k = 0; k < 3; k++) {
            int lit = g_lit[c * 3 + k];
            float sign = (lit < NV) ? 1.f : -1.f;
            int var = (lit < NV) ? lit : lit - NV;
            s += softplus_f(g_logits[var] * sign);
        }
        float cv = expf(-s);
        float l = -logf(1.f - cv + 1e-8f);
        t = l * l;
    }
    for (int o = 16; o; o >>= 1) t += __shfl_down_sync(0xffffffffu, t, o);
    __shared__ float sm[8];
    if ((threadIdx.x & 31) == 0) sm[threadIdx.x >> 5] = t;
    __syncthreads();
    if (threadIdx.x < 8) {
        float v = sm[threadIdx.x];
        for (int o = 4; o; o >>= 1) v += __shfl_down_sync(0xffu, v, o);
        if (threadIdx.x == 0) atomicAdd(&g_loss, v);
    }
}

__global__ void finalize_kernel(float* __restrict__ out, int out_size) {
    int i = blockIdx.x * blockDim.x + threadIdx.x;
    if (i < NV && i < out_size) out[i] = g_logits[i];
    if (i == 0 && out_size > NV) out[NV] = g_loss / (float)ROUNDS;
}

// ---------------------------------------------------------------------------
// Host orchestration
// ---------------------------------------------------------------------------
static const __nv_bfloat16* g_wp_host;

static inline void launch_tg(const __nv_bfloat16* A1, const __nv_bfloat16* A1l,
                             int K1, int off1,
                             const __nv_bfloat16* A2, const __nv_bfloat16* A2l,
                             int K2, int off2,
                             const __nv_bfloat16* A3, const __nv_bfloat16* A3l,
                             int K3, int off3,
                             const float* bias, float* C,
                             __nv_bfloat16* Ch, __nv_bfloat16* Cl,
                             int M, int N, int flags) {
    const __nv_bfloat16* wp = g_wp_host;
    dim3 grid(N / 128, (M + 63) / 64);
    tgemm_kernel<<<grid, 256, TG_SMEM>>>(
        A1, A1l, K1, wp + off1, wp + WTOT + off1,
        A2, A2l, K2, A2 ? wp + off2 : nullptr, A2 ? wp + WTOT + off2 : nullptr,
        A3, A3l, K3, A3 ? wp + off3 : nullptr, A3 ? wp + WTOT + off3 : nullptr,
        bias, C, Ch, Cl, M, N, flags);
}

extern "C" void kernel_launch(void* const* d_in, const int* in_sizes, int n_in,
                              void* d_out, int out_size) {
    int base = (n_in >= 2 && in_sizes[1] == 1) ? 1 : 0;
    const int* clause_lits = (const int*)d_in[0];
    const float* P[26];
    for (int i = 0; i < 26; i++) P[i] = (const float*)d_in[1 + base + i];
    const float *L_init = P[0], *C_init = P[1];
    const float *LC_W0 = P[2], *LC_b0 = P[3], *LC_W1 = P[4], *LC_b1 = P[5],
                *LC_W2 = P[6], *LC_b2 = P[7];
    const float *CL_W0 = P[8], *CL_b0 = P[9], *CL_W1 = P[10], *CL_b1 = P[11],
                *CL_W2 = P[12], *CL_b2 = P[13];
    const float *C_Wx = P[14], *C_Wh = P[15], *C_b = P[16];
    const float *L_Wx = P[17], *L_Wh = P[18], *L_b = P[19];
    const float *V_W0 = P[20], *V_b0 = P[21], *V_W1 = P[22], *V_b1 = P[23],
                *V_W2 = P[24], *V_b2 = P[25];

    __nv_bfloat16 *lhB, *chB, *b1B, *b2B, *msgcB, *msglB, *v1B, *wp;
    float *pre, *zc, *zl, *cc, *lc, *v2;
    cudaGetSymbolAddress((void**)&lhB, g_lhB);
    cudaGetSymbolAddress((void**)&chB, g_chB);
    cudaGetSymbolAddress((void**)&b1B, g_b1B);
    cudaGetSymbolAddress((void**)&b2B, g_b2B);
    cudaGetSymbolAddress((void**)&msgcB, g_msgcB);
    cudaGetSymbolAddress((void**)&msglB, g_msglB);
    cudaGetSymbolAddress((void**)&v1B, g_v1B);
    cudaGetSymbolAddress((void**)&pre, g_pre);
    cudaGetSymbolAddress((void**)&zc, g_zc);
    cudaGetSymbolAddress((void**)&zl, g_zl);
    cudaGetSymbolAddress((void**)&cc, g_cc);
    cudaGetSymbolAddress((void**)&lc, g_lc);
    cudaGetSymbolAddress((void**)&v2, g_v2);
    cudaGetSymbolAddress((void**)&wp, g_wpool);
    g_wp_host = wp;

    // lo-array base pointers
    __nv_bfloat16 *lhL = lhB + (size_t)NL * FM;
    __nv_bfloat16 *chL = chB + (size_t)NC * FM;
    __nv_bfloat16 *b1L = b1B + (size_t)NC * FM;
    __nv_bfloat16 *b2L = b2B + (size_t)NC * FM;
    __nv_bfloat16 *mcL = msgcB + (size_t)NC * FM;
    __nv_bfloat16 *mlL = msglB + (size_t)NL * FM;
    __nv_bfloat16 *v1L = v1B + (size_t)NV * 2 * FM;

    cudaFuncSetAttribute(tgemm_kernel, cudaFuncAttributeMaxDynamicSharedMemorySize,
                         TG_SMEM);

    // weight pool offsets ([N,K] transposed, element offsets)
    const int oLC0 = 0, oLC1 = 65536, oLC2 = 131072;
    const int oCL0 = 196608, oCL1 = 262144, oCL2 = 327680;
    const int oCWx = 393216, oCWh = 655360;
    const int oLWxa = 917504, oLWxb = 1179648, oLWh = 1441792;
    const int oVW0a = 1703936, oVW0b = 1835008, oVW1 = 1966080;

    struct { const float* src; int K, N, off; } WS[14] = {
        {LC_W0, 256, 256, oLC0}, {LC_W1, 256, 256, oLC1}, {LC_W2, 256, 256, oLC2},
        {CL_W0, 256, 256, oCL0}, {CL_W1, 256, 256, oCL1}, {CL_W2, 256, 256, oCL2},
        {C_Wx, 256, 1024, oCWx}, {C_Wh, 256, 1024, oCWh},
        {L_Wx, 256, 1024, oLWxa}, {L_Wx + 256 * 1024, 256, 1024, oLWxb},
        {L_Wh, 256, 1024, oLWh},
        {V_W0, 256, 512, oVW0a}, {V_W0 + 256 * 512, 256, 512, oVW0b},
        {V_W1, 512, 512, oVW1},
    };
    for (int i = 0; i < 14; i++) {
        int n = WS[i].K * WS[i].N;
        wsplit_kernel<<<(n + 255) / 256, 256>>>(WS[i].src, WS[i].K, WS[i].N,
                                                WS[i].off);
    }

    // preprocessing
    edge_prep_kernel<<<(NE + 255) / 256, 256>>>(clause_lits);
    zero_cnt_kernel<<<(NL + 255) / 256, 256>>>();
    count_kernel<<<(NE + 255) / 256, 256>>>();
    scan_kernel<<<1, 1024>>>();
    zero_cnt_kernel<<<(NL + 255) / 256, 256>>>();
    fill_kernel<<<(NE + 255) / 256, 256>>>();
    sort_kernel<<<(NL + 127) / 128, 128>>>();
    init_state_kernel<<<(NC * FM + 255) / 256, 256>>>(L_init, C_init);

    for (int r = 0; r < ROUNDS; r++) {
        // literal -> clause MLP (split bf16 intermediates)
        launch_tg(lhB, lhL, 256, oLC0, nullptr, nullptr, 0, 0,
                  nullptr, nullptr, 0, 0,
                  LC_b0, nullptr, b1B, b1L, NL, 256, GF_RELU | GF_SPLIT);
        launch_tg(b1B, b1L, 256, oLC1, nullptr, nullptr, 0, 0,
                  nullptr, nullptr, 0, 0,
                  LC_b1, nullptr, b2B, b2L, NL, 256, GF_RELU | GF_SPLIT);
        launch_tg(b2B, b2L, 256, oLC2, nullptr, nullptr, 0, 0,
                  nullptr, nullptr, 0, 0,
                  LC_b2, pre, nullptr, nullptr, NL, 256, 0);
        clause_gather_kernel<<<NC, FM>>>(pre, msgcB);

        // clause LSTM (fused x/h GEMM, K=512)
        launch_tg(msgcB, mcL, 256, oCWx, chB, chL, 256, oCWh,
                  nullptr, nullptr, 0, 0,
                  C_b, zc, nullptr, nullptr, NC, 1024, 0);
        lstm_kernel<<<(NC * FM + 255) / 256, 256>>>(zc, chB, (size_t)NC * FM,
                                                    cc, NC);

        // clause -> literal MLP
        launch_tg(chB, chL, 256, oCL0, nullptr, nullptr, 0, 0,
                  nullptr, nullptr, 0, 0,
                  CL_b0, nullptr, b1B, b1L, NC, 256, GF_RELU | GF_SPLIT);
        launch_tg(b1B, b1L, 256, oCL1, nullptr, nullptr, 0, 0,
                  nullptr, nullptr, 0, 0,
                  CL_b1, nullptr, b2B, b2L, NC, 256, GF_RELU | GF_SPLIT);
        launch_tg(b2B, b2L, 256, oCL2, nullptr, nullptr, 0, 0,
                  nullptr, nullptr, 0, 0,
                  CL_b2, pre, nullptr, nullptr, NC, 256, 0);
        lit_gather_kernel<<<NL, FM>>>(pre, msglB);

        // literal LSTM: z = [msgl, flipped(lh), lh] @ rows(LWxa, LWxb, LWh)
        launch_tg(msglB, mlL, 256, oLWxa, lhB, lhL, 256, oLWxb,
                  lhB, lhL, 256, oLWh,
                  L_b, zl, nullptr, nullptr, NL, 1024, GF_FLIP2);
        lstm_kernel<<<(NL * FM + 255) / 256, 256>>>(zl, lhB, (size_t)NL * FM,
                                                    lc, NL);

        // vote: x = [lh[:NV], lh[NV:]] along K
        launch_tg(lhB, lhL, 256, oVW0a,
                  lhB + (size_t)NV * FM, lhL + (size_t)NV * FM, 256, oVW0b,
                  nullptr, nullptr, 0, 0,
                  V_b0, nullptr, v1B, v1L, NV, 512, GF_RELU | GF_SPLIT);
        launch_tg(v1B, v1L, 512, oVW1, nullptr, nullptr, 0, 0,
                  nullptr, nullptr, 0, 0,
                  V_b1, v2, nullptr, nullptr, NV, 512, GF_RELU);
        vote_out_kernel<<<NV, 128>>>(v2, V_W2, V_b2);
        loss_kernel<<<(NC + 255) / 256, 256>>>();
    }

    finalize_kernel<<<(NV + 255) / 256, 256>>>((float*)d_out, out_size);
}

// round 17
// speedup vs baseline: 1.0415x; 1.0415x over previous
#include <cuda_runtime.h>
#include <cuda_bf16.h>
#include <math.h>
#include <stdint.h>

#define NV 4000
#define NL 8000          // 2*NV literals
#define NC 16800
#define NE 50400         // NC*3 edges
#define FM 256
#define ROUNDS 32

// ---------------------------------------------------------------------------
// PTX helpers (baseline ISA only: ldmatrix + mma.sync + cp.async, sm_80+)
// ---------------------------------------------------------------------------
__device__ __forceinline__ uint32_t smem_u32(const void* p) {
    uint32_t a;
    asm("{ .reg .u64 t; cvta.to.shared.u64 t, %1; cvt.u32.u64 %0, t; }"
        : "=r"(a) : "l"(p));
    return a;
}
__device__ __forceinline__ void ldsm_x4(uint32_t& r0, uint32_t& r1,
                                        uint32_t& r2, uint32_t& r3, uint32_t a) {
    asm volatile("ldmatrix.sync.aligned.m8n8.x4.shared.b16 {%0,%1,%2,%3}, [%4];"
                 : "=r"(r0), "=r"(r1), "=r"(r2), "=r"(r3) : "r"(a));
}
__device__ __forceinline__ void ldsm_x2(uint32_t& r0, uint32_t& r1, uint32_t a) {
    asm volatile("ldmatrix.sync.aligned.m8n8.x2.shared.b16 {%0,%1}, [%2];"
                 : "=r"(r0), "=r"(r1) : "r"(a));
}
__device__ __forceinline__ void mma_bf16(float* c, const uint32_t* a,
                                         const uint32_t* b) {
    asm volatile(
        "mma.sync.aligned.m16n8k16.row.col.f32.bf16.bf16.f32 "
        "{%0,%1,%2,%3}, {%4,%5,%6,%7}, {%8,%9}, {%0,%1,%2,%3};"
        : "+f"(c[0]), "+f"(c[1]), "+f"(c[2]), "+f"(c[3])
        : "r"(a[0]), "r"(a[1]), "r"(a[2]), "r"(a[3]), "r"(b[0]), "r"(b[1]));
}
__device__ __forceinline__ void cpasync16(uint32_t saddr, const void* g) {
    asm volatile("cp.async.cg.shared.global [%0], [%1], 16;"
                 :: "r"(saddr), "l"(g) : "memory");
}
__device__ __forceinline__ void cpasync16z(uint32_t saddr, const void* g, int ssz) {
    asm volatile("cp.async.cg.shared.global [%0], [%1], 16, %2;"
                 :: "r"(saddr), "l"(g), "r"(ssz) : "memory");
}
#define CPASYNC_COMMIT() asm volatile("cp.async.commit_group;" ::: "memory")
#define CPASYNC_WAIT0()  asm volatile("cp.async.wait_group 0;" ::: "memory")

#define SWZ128(off) ((off) ^ (((off) >> 3) & 0x70))

// ---------------------------------------------------------------------------
// Scratch (static device globals)
// Activations are stored PRE-SPLIT as bf16 hi/lo pairs (hi array, then lo).
// ---------------------------------------------------------------------------
__device__ __nv_bfloat16 g_lhB[2 * NL * FM];
__device__ __nv_bfloat16 g_chB[2 * NC * FM];
__device__ __nv_bfloat16 g_b1B[2 * NC * FM];
__device__ __nv_bfloat16 g_b2B[2 * NC * FM];
__device__ __nv_bfloat16 g_msgcB[2 * NC * FM];
__device__ __nv_bfloat16 g_msglB[2 * NL * FM];
__device__ __nv_bfloat16 g_v1B[2 * NV * 2 * FM];
__device__ float g_pre[NC * FM];     // fp32 MLP output feeding gathers
__device__ float g_zc[NC * 4 * FM];
__device__ float g_zl[NL * 4 * FM];
__device__ float g_cc[NC * FM];
__device__ float g_lc[NL * FM];
__device__ float g_v2[NV * 2 * FM];
__device__ float g_logits[NV];
__device__ float g_loss;

__device__ int g_lit[NE];
__device__ int g_cnt[NL];
__device__ int g_off[NL + 1];
__device__ int g_ledges[NE];

// weight pool: transposed [N,K] bf16, hi then lo halves
#define WTOT 2228224
__device__ __nv_bfloat16 g_wpool[2 * WTOT];

__device__ __forceinline__ void split_write(__nv_bfloat16* hi, __nv_bfloat16* lo,
                                            size_t idx, float v) {
    __nv_bfloat16 h = __float2bfloat16_rn(v);
    hi[idx] = h;
    lo[idx] = __float2bfloat16_rn(v - __bfloat162float(h));
}

// ---------------------------------------------------------------------------
// Edge preprocessing (unchanged, known-correct)
// ---------------------------------------------------------------------------
__global__ void edge_prep_kernel(const int* __restrict__ lits) {
    int e = blockIdx.x * blockDim.x + threadIdx.x;
    if (e >= NE) return;
    int v = lits[e];
    int va = (v > 0 ? v : -v) - 1;
    g_lit[e] = (v > 0) ? va : (NV + va);
}
__global__ void zero_cnt_kernel() {
    int i = blockIdx.x * blockDim.x + threadIdx.x;
    if (i < NL) g_cnt[i] = 0;
}
__global__ void count_kernel() {
    int e = blockIdx.x * blockDim.x + threadIdx.x;
    if (e < NE) atomicAdd(&g_cnt[g_lit[e]], 1);
}
__global__ void scan_kernel() {
    __shared__ int part[1024];
    const int t = threadIdx.x;
    const int CH = 8;
    int base = t * CH;
    int local[CH];
    int s = 0;
    #pragma unroll
    for (int i = 0; i < CH; i++) {
        int idx = base + i;
        int v = (idx < NL) ? g_cnt[idx] : 0;
        local[i] = s;
        s += v;
    }
    part[t] = s;
    __syncthreads();
    for (int d = 1; d < 1024; d <<= 1) {
        int v = (t >= d) ? part[t - d] : 0;
        __syncthreads();
        part[t] += v;
        __syncthreads();
    }
    int off = (t == 0) ? 0 : part[t - 1];
    #pragma unroll
    for (int i = 0; i < CH; i++) {
        int idx = base + i;
        if (idx < NL) g_off[idx] = off + local[i];
    }
    if (t == 1023) g_off[NL] = part[1023];
}
__global__ void fill_kernel() {
    int e = blockIdx.x * blockDim.x + threadIdx.x;
    if (e >= NE) return;
    int l = g_lit[e];
    int pos = atomicAdd(&g_cnt[l], 1);
    g_ledges[g_off[l] + pos] = e;
}
__global__ void sort_kernel() {
    int l = blockIdx.x * blockDim.x + threadIdx.x;
    if (l >= NL) return;
    int beg = g_off[l], end = g_off[l + 1];
    for (int i = beg + 1; i < end; i++) {
        int key = g_ledges[i];
        int j = i - 1;
        while (j >= beg && g_ledges[j] > key) {
            g_ledges[j + 1] = g_ledges[j];
            j--;
        }
        g_ledges[j + 1] = key;
    }
}
__global__ void init_state_kernel(const float* __restrict__ Li,
                                  const float* __restrict__ Ci) {
    int idx = blockIdx.x * blockDim.x + threadIdx.x;
    const float inv = 0.0625f;
    if (idx < NL * FM) {
        split_write(g_lhB, g_lhB + NL * FM, idx, Li[idx & (FM - 1)] * inv);
        g_lc[idx] = 0.f;
    }
    if (idx < NC * FM) {
        split_write(g_chB, g_chB + NC * FM, idx, Ci[idx & (FM - 1)] * inv);
        g_cc[idx] = 0.f;
    }
    if (idx == 0) g_loss = 0.f;
}

// ---------------------------------------------------------------------------
// Weight split+transpose: src fp32 [K,N] -> pool hi/lo bf16 [N,K]
// ---------------------------------------------------------------------------
__global__ void wsplit_kernel(const float* __restrict__ src, int K, int N, int off) {
    int idx = blockIdx.x * blockDim.x + threadIdx.x;
    if (idx >= K * N) return;
    int k = idx / N, n = idx - k * N;
    float v = src[idx];
    __nv_bfloat16 h = __float2bfloat16_rn(v);
    __nv_bfloat16 l = __float2bfloat16_rn(v - __bfloat162float(h));
    g_wpool[off + (size_t)n * K + k] = h;
    g_wpool[WTOT + off + (size_t)n * K + k] = l;
}

// ---------------------------------------------------------------------------
// Tensor-core GEMM (mma.sync bf16, fp32 accum, Markidis 3-term split):
//   C[M,N] = concat_K(A1,A2,A3) @ concat_rows(W1,W2,W3) (+bias)(relu)
// Templated on BM: 128 (2 CTAs/SM, for large M) or 64 (3 CTAs/SM, small M).
// A inputs are PRE-SPLIT bf16 hi/lo [M,K]; staging is pure cp.async.
// GF_FLIP2: segment-2 rows read flip-permuted (l<NV -> l+NV else l-NV).
// GF_SPLIT: output written as split bf16 hi/lo (Ch/Cl) instead of fp32 C.
// ---------------------------------------------------------------------------
#define GF_RELU 1
#define GF_FLIP2 4
#define GF_SPLIT 16

template <int BM>
__global__ __launch_bounds__(256, (BM == 128) ? 2 : 3)
void tgemm_kernel(const __nv_bfloat16* __restrict__ A1h,
                  const __nv_bfloat16* __restrict__ A1l, int K1,
                  const __nv_bfloat16* __restrict__ B1h,
                  const __nv_bfloat16* __restrict__ B1l,
                  const __nv_bfloat16* __restrict__ A2h,
                  const __nv_bfloat16* __restrict__ A2l, int K2,
                  const __nv_bfloat16* __restrict__ B2h,
                  const __nv_bfloat16* __restrict__ B2l,
                  const __nv_bfloat16* __restrict__ A3h,
                  const __nv_bfloat16* __restrict__ A3l, int K3,
                  const __nv_bfloat16* __restrict__ B3h,
                  const __nv_bfloat16* __restrict__ B3l,
                  const float* __restrict__ bias, float* __restrict__ C,
                  __nv_bfloat16* __restrict__ Ch, __nv_bfloat16* __restrict__ Cl,
                  int M, int N, int flags) {
    constexpr int MT = BM / 32;            // m16 tiles per warp
    constexpr int ABYTES = BM * 128;       // one A half-tile
    constexpr int AIT = BM / 16;           // A staging iterations (hi+lo)
    constexpr int ASH = (BM == 128) ? 10 : 9;   // half-select shift

    extern __shared__ char smem[];
    const uint32_t sb0 = smem_u32(smem);
    const uint32_t sAh = sb0, sAl = sb0 + ABYTES;
    const uint32_t sBh = sb0 + 2 * ABYTES, sBl = sBh + 16384;

    const int tid = threadIdx.x;
    const int wid = tid >> 5, lid = tid & 31;
    const int bm = blockIdx.y * BM;
    const int bn = blockIdx.x * 128;
    const int wm = (wid & 1) * (BM / 2);
    const int wn = (wid >> 1) * 32;

    float acc[MT][4][4];
    #pragma unroll
    for (int i = 0; i < MT; i++)
        #pragma unroll
        for (int j = 0; j < 4; j++)
            #pragma unroll
            for (int q = 0; q < 4; q++) acc[i][j][q] = 0.f;

    const int nch = (K1 + K2 + K3) >> 6;

    for (int c = 0; c < nch; c++) {
        int kk0 = c << 6;
        const __nv_bfloat16 *ah = A1h, *al = A1l, *bh = B1h, *bl = B1l;
        int ldk = K1, kk = kk0, flip = 0;
        if (kk0 >= K1 + K2) {
            ah = A3h; al = A3l; bh = B3h; bl = B3l; ldk = K3; kk = kk0 - K1 - K2;
        } else if (kk0 >= K1) {
            ah = A2h; al = A2l; bh = B2h; bl = B2l; ldk = K2;
            kk = kk0 - K1; flip = (flags & GF_FLIP2);
        }

        __syncthreads();   // protect tiles from previous iteration's readers

        // ---- A stage: pure cp.async copy of pre-split bf16 (swizzled) ----
        #pragma unroll
        for (int i = 0; i < AIT; i++) {
            int idx = i * 256 + tid;
            int half = idx >> ASH;             // 0: hi, 1: lo
            int j = idx & ((1 << ASH) - 1);
            int row = j >> 3;                  // m local
            int c16 = (j & 7) << 4;            // byte offset 0..112
            int gr = bm + row;
            int inb = (gr < M);
            int ar = inb ? gr : 0;
            if (flip) ar = (ar < NV) ? ar + NV : ar - NV;
            const __nv_bfloat16* src =
                (half ? al : ah) + (size_t)ar * ldk + kk + (c16 >> 1);
            cpasync16z((half ? sAl : sAh) + SWZ128((uint32_t)(row * 128 + c16)),
                       src, inb ? 16 : 0);
        }

        // ---- B stage: cp.async copy (swizzled), 128 rows hi+lo ----
        #pragma unroll
        for (int i = 0; i < 8; i++) {
            int idx = i * 256 + tid;
            int half = idx >> 10;
            int j = idx & 1023;
            int row = j >> 3;                  // n local 0..127
            int c16 = (j & 7) << 4;
            const __nv_bfloat16* src =
                (half ? bl : bh) + (size_t)(bn + row) * ldk + kk + (c16 >> 1);
            cpasync16((half ? sBl : sBh) + SWZ128((uint32_t)(row * 128 + c16)),
                      src);
        }
        CPASYNC_COMMIT();
        CPASYNC_WAIT0();
        __syncthreads();

        // ---- compute: 4 k16 steps ----
        #pragma unroll
        for (int s = 0; s < 4; s++) {
            int kb = s * 32;
            uint32_t ahf[MT][4], alf[MT][4], bhf[4][2], blf[4][2];
            int arow = (lid & 15);
            int acolb = kb + (lid >> 4) * 16;
            #pragma unroll
            for (int mt = 0; mt < MT; mt++) {
                uint32_t o = SWZ128((uint32_t)((wm + mt * 16 + arow) * 128 + acolb));
                ldsm_x4(ahf[mt][0], ahf[mt][1], ahf[mt][2], ahf[mt][3], sAh + o);
                ldsm_x4(alf[mt][0], alf[mt][1], alf[mt][2], alf[mt][3], sAl + o);
            }
            int brow = (lid & 7);
            int bcolb = kb + ((lid >> 3) & 1) * 16;
            #pragma unroll
            for (int nt = 0; nt < 4; nt++) {
                uint32_t o = SWZ128((uint32_t)((wn + nt * 8 + brow) * 128 + bcolb));
                ldsm_x2(bhf[nt][0], bhf[nt][1], sBh + o);
                ldsm_x2(blf[nt][0], blf[nt][1], sBl + o);
            }
            #pragma unroll
            for (int mt = 0; mt < MT; mt++)
                #pragma unroll
                for (int nt = 0; nt < 4; nt++) {
                    mma_bf16(acc[mt][nt], ahf[mt], bhf[nt]);
                    mma_bf16(acc[mt][nt], alf[mt], bhf[nt]);
                    mma_bf16(acc[mt][nt], ahf[mt], blf[nt]);
                }
        }
    }

    // ---- epilogue ----
    #pragma unroll
    for (int mt = 0; mt < MT; mt++) {
        int r0 = bm + wm + mt * 16 + (lid >> 2);
        #pragma unroll
        for (int nt = 0; nt < 4; nt++) {
            int col = bn + wn + nt * 8 + (lid & 3) * 2;
            float bx = 0.f, by = 0.f;
            if (bias) { bx = bias[col]; by = bias[col + 1]; }
            float2 v0 = make_float2(acc[mt][nt][0] + bx, acc[mt][nt][1] + by);
            float2 v1 = make_float2(acc[mt][nt][2] + bx, acc[mt][nt][3] + by);
            if (flags & GF_RELU) {
                v0.x = fmaxf(v0.x, 0.f); v0.y = fmaxf(v0.y, 0.f);
                v1.x = fmaxf(v1.x, 0.f); v1.y = fmaxf(v1.y, 0.f);
            }
            if (flags & GF_SPLIT) {
                if (r0 < M) {
                    size_t ix = (size_t)r0 * N + col;
                    __nv_bfloat16 h0 = __float2bfloat16_rn(v0.x);
                    __nv_bfloat16 h1 = __float2bfloat16_rn(v0.y);
                    __nv_bfloat162 hi = __halves2bfloat162(h0, h1);
                    *(uint32_t*)&Ch[ix] = *(uint32_t*)&hi;
                    __nv_bfloat162 lo = __halves2bfloat162(
                        __float2bfloat16_rn(v0.x - __bfloat162float(h0)),
                        __float2bfloat16_rn(v0.y - __bfloat162float(h1)));
                    *(uint32_t*)&Cl[ix] = *(uint32_t*)&lo;
                }
                if (r0 + 8 < M) {
                    size_t ix = (size_t)(r0 + 8) * N + col;
                    __nv_bfloat16 h0 = __float2bfloat16_rn(v1.x);
                    __nv_bfloat16 h1 = __float2bfloat16_rn(v1.y);
                    __nv_bfloat162 hi = __halves2bfloat162(h0, h1);
                    *(uint32_t*)&Ch[ix] = *(uint32_t*)&hi;
                    __nv_bfloat162 lo = __halves2bfloat162(
                        __float2bfloat16_rn(v1.x - __bfloat162float(h0)),
                        __float2bfloat16_rn(v1.y - __bfloat162float(h1)));
                    *(uint32_t*)&Cl[ix] = *(uint32_t*)&lo;
                }
            } else {
                if (r0 < M)     *(float2*)&C[(size_t)r0 * N + col] = v0;
                if (r0 + 8 < M) *(float2*)&C[(size_t)(r0 + 8) * N + col] = v1;
            }
        }
    }
}

// ---------------------------------------------------------------------------
// Elementwise / gather kernels
// ---------------------------------------------------------------------------
__device__ __forceinline__ float sigm(float x) { return 1.f / (1.f + expf(-x)); }

// LSTM elementwise: z fp32 (gate-blocked), c fp32 in/out, h written SPLIT bf16.
__global__ void lstm_kernel(const float* __restrict__ z,
                            __nv_bfloat16* __restrict__ hB, size_t loOff,
                            float* __restrict__ c, int R) {
    int idx = blockIdx.x * blockDim.x + threadIdx.x;
    if (idx >= R * FM) return;
    int r = idx / FM, f = idx - r * FM;
    const float* zr = z + (size_t)r * 4 * FM;
    float zi = zr[f], zf = zr[FM + f], zg = zr[2 * FM + f], zo = zr[3 * FM + f];
    float cv = sigm(zf) * c[idx] + sigm(zi) * tanhf(zg);
    c[idx] = cv;
    float hv = sigm(zo) * tanhf(cv);
    split_write(hB, hB + loOff, idx, hv);
}

__global__ void clause_gather_kernel(const float* __restrict__ pre,
                                     __nv_bfloat16* __restrict__ outB) {
    int c = blockIdx.x;
    int f = threadIdx.x;
    int e0 = c * 3;
    float s = pre[(size_t)g_lit[e0] * FM + f] +
              pre[(size_t)g_lit[e0 + 1] * FM + f] +
              pre[(size_t)g_lit[e0 + 2] * FM + f];
    split_write(outB, outB + (size_t)NC * FM, (size_t)c * FM + f, s);
}

__global__ void lit_gather_kernel(const float* __restrict__ cl_pre,
                                  __nv_bfloat16* __restrict__ outB) {
    int l = blockIdx.x;
    int f = threadIdx.x;
    int beg = g_off[l], end = g_off[l + 1];
    float s = 0.f;
    for (int i = beg; i < end; i++) {
        int e = g_ledges[i];
        s += cl_pre[(size_t)(e / 3) * FM + f];
    }
    split_write(outB, outB + (size_t)NL * FM, (size_t)l * FM + f, s);
}

__global__ void vote_out_kernel(const float* __restrict__ H,
                                const float* __restrict__ W,
                                const float* __restrict__ b) {
    int r = blockIdx.x;
    float s = 0.f;
    for (int k = threadIdx.x; k < 2 * FM; k += blockDim.x)
        s += H[(size_t)r * 2 * FM + k] * W[k];
    for (int o = 16; o; o >>= 1) s += __shfl_down_sync(0xffffffffu, s, o);
    __shared__ float sm[4];
    if ((threadIdx.x & 31) == 0) sm[threadIdx.x >> 5] = s;
    __syncthreads();
    if (threadIdx.x == 0)
        g_logits[r] = sm[0] + sm[1] + sm[2] + sm[3] + b[0];
}

__device__ __forceinline__ float softplus_f(float x) {
    return x > 0.f ? x + log1pf(expf(-x)) : log1pf(expf(x));
}

__global__ void loss_kernel() {
    int c = blockIdx.x * blockDim.x + threadIdx.x;
    float t = 0.f;
    if (c < NC) {
        float s = 0.f;
        #pragma unroll
        for (int k = 0; k < 3; k++) {
            int lit = g_lit[c * 3 + k];
            float sign = (lit < NV) ? 1.f : -1.f;
            int var = (lit < NV) ? lit : lit - NV;
            s += softplus_f(g_logits[var] * sign);
        }
        float cv = expf(-s);
        float l = -logf(1.f - cv + 1e-8f);
        t = l * l;
    }
    for (int o = 16; o; o >>= 1) t += __shfl_down_sync(0xffffffffu, t, o);
    __shared__ float sm[8];
    if ((threadIdx.x & 31) == 0) sm[threadIdx.x >> 5] = t;
    __syncthreads();
    if (threadIdx.x < 8) {
        float v = sm[threadIdx.x];
        for (int o = 4; o; o >>= 1) v += __shfl_down_sync(0xffu, v, o);
        if (threadIdx.x == 0) atomicAdd(&g_loss, v);
    }
}

__global__ void finalize_kernel(float* __restrict__ out, int out_size) {
    int i = blockIdx.x * blockDim.x + threadIdx.x;
    if (i < NV && i < out_size) out[i] = g_logits[i];
    if (i == 0 && out_size > NV) out[NV] = g_loss / (float)ROUNDS;
}

// ---------------------------------------------------------------------------
// Host orchestration
// ---------------------------------------------------------------------------
static const __nv_bfloat16* g_wp_host;

static inline void launch_tg(const __nv_bfloat16* A1, const __nv_bfloat16* A1l,
                             int K1, int off1,
                             const __nv_bfloat16* A2, const __nv_bfloat16* A2l,
                             int K2, int off2,
                             const __nv_bfloat16* A3, const __nv_bfloat16* A3l,
                             int K3, int off3,
                             const float* bias, float* C,
                             __nv_bfloat16* Ch, __nv_bfloat16* Cl,
                             int M, int N, int flags) {
    const __nv_bfloat16* wp = g_wp_host;
    if (M > 8000) {
        dim3 grid(N / 128, (M + 127) / 128);
        tgemm_kernel<128><<<grid, 256, 65536>>>(
            A1, A1l, K1, wp + off1, wp + WTOT + off1,
            A2, A2l, K2, A2 ? wp + off2 : nullptr, A2 ? wp + WTOT + off2 : nullptr,
            A3, A3l, K3, A3 ? wp + off3 : nullptr, A3 ? wp + WTOT + off3 : nullptr,
            bias, C, Ch, Cl, M, N, flags);
    } else {
        dim3 grid(N / 128, (M + 63) / 64);
        tgemm_kernel<64><<<grid, 256, 49152>>>(
            A1, A1l, K1, wp + off1, wp + WTOT + off1,
            A2, A2l, K2, A2 ? wp + off2 : nullptr, A2 ? wp + WTOT + off2 : nullptr,
            A3, A3l, K3, A3 ? wp + off3 : nullptr, A3 ? wp + WTOT + off3 : nullptr,
            bias, C, Ch, Cl, M, N, flags);
    }
}

extern "C" void kernel_launch(void* const* d_in, const int* in_sizes, int n_in,
                              void* d_out, int out_size) {
    int base = (n_in >= 2 && in_sizes[1] == 1) ? 1 : 0;
    const int* clause_lits = (const int*)d_in[0];
    const float* P[26];
    for (int i = 0; i < 26; i++) P[i] = (const float*)d_in[1 + base + i];
    const float *L_init = P[0], *C_init = P[1];
    const float *LC_W0 = P[2], *LC_b0 = P[3], *LC_W1 = P[4], *LC_b1 = P[5],
                *LC_W2 = P[6], *LC_b2 = P[7];
    const float *CL_W0 = P[8], *CL_b0 = P[9], *CL_W1 = P[10], *CL_b1 = P[11],
                *CL_W2 = P[12], *CL_b2 = P[13];
    const float *C_Wx = P[14], *C_Wh = P[15], *C_b = P[16];
    const float *L_Wx = P[17], *L_Wh = P[18], *L_b = P[19];
    const float *V_W0 = P[20], *V_b0 = P[21], *V_W1 = P[22], *V_b1 = P[23],
                *V_W2 = P[24], *V_b2 = P[25];

    __nv_bfloat16 *lhB, *chB, *b1B, *b2B, *msgcB, *msglB, *v1B, *wp;
    float *pre, *zc, *zl, *cc, *lc, *v2;
    cudaGetSymbolAddress((void**)&lhB, g_lhB);
    cudaGetSymbolAddress((void**)&chB, g_chB);
    cudaGetSymbolAddress((void**)&b1B, g_b1B);
    cudaGetSymbolAddress((void**)&b2B, g_b2B);
    cudaGetSymbolAddress((void**)&msgcB, g_msgcB);
    cudaGetSymbolAddress((void**)&msglB, g_msglB);
    cudaGetSymbolAddress((void**)&v1B, g_v1B);
    cudaGetSymbolAddress((void**)&pre, g_pre);
    cudaGetSymbolAddress((void**)&zc, g_zc);
    cudaGetSymbolAddress((void**)&zl, g_zl);
    cudaGetSymbolAddress((void**)&cc, g_cc);
    cudaGetSymbolAddress((void**)&lc, g_lc);
    cudaGetSymbolAddress((void**)&v2, g_v2);
    cudaGetSymbolAddress((void**)&wp, g_wpool);
    g_wp_host = wp;

    // lo-array base pointers
    __nv_bfloat16 *lhL = lhB + (size_t)NL * FM;
    __nv_bfloat16 *chL = chB + (size_t)NC * FM;
    __nv_bfloat16 *b1L = b1B + (size_t)NC * FM;
    __nv_bfloat16 *b2L = b2B + (size_t)NC * FM;
    __nv_bfloat16 *mcL = msgcB + (size_t)NC * FM;
    __nv_bfloat16 *mlL = msglB + (size_t)NL * FM;
    __nv_bfloat16 *v1L = v1B + (size_t)NV * 2 * FM;

    cudaFuncSetAttribute(tgemm_kernel<128>,
                         cudaFuncAttributeMaxDynamicSharedMemorySize, 65536);
    cudaFuncSetAttribute(tgemm_kernel<64>,
                         cudaFuncAttributeMaxDynamicSharedMemorySize, 49152);

    // weight pool offsets ([N,K] transposed, element offsets)
    const int oLC0 = 0, oLC1 = 65536, oLC2 = 131072;
    const int oCL0 = 196608, oCL1 = 262144, oCL2 = 327680;
    const int oCWx = 393216, oCWh = 655360;
    const int oLWxa = 917504, oLWxb = 1179648, oLWh = 1441792;
    const int oVW0a = 1703936, oVW0b = 1835008, oVW1 = 1966080;

    struct { const float* src; int K, N, off; } WS[14] = {
        {LC_W0, 256, 256, oLC0}, {LC_W1, 256, 256, oLC1}, {LC_W2, 256, 256, oLC2},
        {CL_W0, 256, 256, oCL0}, {CL_W1, 256, 256, oCL1}, {CL_W2, 256, 256, oCL2},
        {C_Wx, 256, 1024, oCWx}, {C_Wh, 256, 1024, oCWh},
        {L_Wx, 256, 1024, oLWxa}, {L_Wx + 256 * 1024, 256, 1024, oLWxb},
        {L_Wh, 256, 1024, oLWh},
        {V_W0, 256, 512, oVW0a}, {V_W0 + 256 * 512, 256, 512, oVW0b},
        {V_W1, 512, 512, oVW1},
    };
    for (int i = 0; i < 14; i++) {
        int n = WS[i].K * WS[i].N;
        wsplit_kernel<<<(n + 255) / 256, 256>>>(WS[i].src, WS[i].K, WS[i].N,
                                                WS[i].off);
    }

    // preprocessing
    edge_prep_kernel<<<(NE + 255) / 256, 256>>>(clause_lits);
    zero_cnt_kernel<<<(NL + 255) / 256, 256>>>();
    count_kernel<<<(NE + 255) / 256, 256>>>();
    scan_kernel<<<1, 1024>>>();
    zero_cnt_kernel<<<(NL + 255) / 256, 256>>>();
    fill_kernel<<<(NE + 255) / 256, 256>>>();
    sort_kernel<<<(NL + 127) / 128, 128>>>();
    init_state_kernel<<<(NC * FM + 255) / 256, 256>>>(L_init, C_init);

    for (int r = 0; r < ROUNDS; r++) {
        // literal -> clause MLP (M=8000 -> 64-tile kernel)
        launch_tg(lhB, lhL, 256, oLC0, nullptr, nullptr, 0, 0,
                  nullptr, nullptr, 0, 0,
                  LC_b0, nullptr, b1B, b1L, NL, 256, GF_RELU | GF_SPLIT);
        launch_tg(b1B, b1L, 256, oLC1, nullptr, nullptr, 0, 0,
                  nullptr, nullptr, 0, 0,
                  LC_b1, nullptr, b2B, b2L, NL, 256, GF_RELU | GF_SPLIT);
        launch_tg(b2B, b2L, 256, oLC2, nullptr, nullptr, 0, 0,
                  nullptr, nullptr, 0, 0,
                  LC_b2, pre, nullptr, nullptr, NL, 256, 0);
        clause_gather_kernel<<<NC, FM>>>(pre, msgcB);

        // clause LSTM (fused x/h GEMM, K=512; M=16800 -> 128-tile kernel)
        launch_tg(msgcB, mcL, 256, oCWx, chB, chL, 256, oCWh,
                  nullptr, nullptr, 0, 0,
                  C_b, zc, nullptr, nullptr, NC, 1024, 0);
        lstm_kernel<<<(NC * FM + 255) / 256, 256>>>(zc, chB, (size_t)NC * FM,
                                                    cc, NC);

        // clause -> literal MLP (M=16800 -> 128-tile kernel)
        launch_tg(chB, chL, 256, oCL0, nullptr, nullptr, 0, 0,
                  nullptr, nullptr, 0, 0,
                  CL_b0, nullptr, b1B, b1L, NC, 256, GF_RELU | GF_SPLIT);
        launch_tg(b1B, b1L, 256, oCL1, nullptr, nullptr, 0, 0,
                  nullptr, nullptr, 0, 0,
                  CL_b1, nullptr, b2B, b2L, NC, 256, GF_RELU | GF_SPLIT);
        launch_tg(b2B, b2L, 256, oCL2, nullptr, nullptr, 0, 0,
                  nullptr, nullptr, 0, 0,
                  CL_b2, pre, nullptr, nullptr, NC, 256, 0);
        lit_gather_kernel<<<NL, FM>>>(pre, msglB);

        // literal LSTM: z = [msgl, flipped(lh), lh] (M=8000 -> 64-tile)
        launch_tg(msglB, mlL, 256, oLWxa, lhB, lhL, 256, oLWxb,
                  lhB, lhL, 256, oLWh,
                  L_b, zl, nullptr, nullptr, NL, 1024, GF_FLIP2);
        lstm_kernel<<<(NL * FM + 255) / 256, 256>>>(zl, lhB, (size_t)NL * FM,
                                                    lc, NL);

        // vote: x = [lh[:NV], lh[NV:]] along K (M=4000 -> 64-tile)
        launch_tg(lhB, lhL, 256, oVW0a,
                  lhB + (size_t)NV * FM, lhL + (size_t)NV * FM, 256, oVW0b,
                  nullptr, nullptr, 0, 0,
                  V_b0, nullptr, v1B, v1L, NV, 512, GF_RELU | GF_SPLIT);
        launch_tg(v1B, v1L, 512, oVW1, nullptr, nullptr, 0, 0,
                  nullptr, nullptr, 0, 0,
                  V_b1, v2, nullptr, nullptr, NV, 512, GF_RELU);
        vote_out_kernel<<<NV, 128>>>(v2, V_W2, V_b2);
        loss_kernel<<<(NC + 255) / 256, 256>>>();
    }

    finalize_kernel<<<(NV + 255) / 256, 256>>>((float*)d_out, out_size);
}